// round 2
// baseline (speedup 1.0000x reference)
#include <cuda_runtime.h>
#include <cuda_bf16.h>
#include <math.h>

// ---------------------------------------------------------------------------
// VQ-VAE forward on GB300 — fp32 SIMT baseline (capture-hardened)
// Stages: enc GEMM1(relu) -> enc GEMM2 -> VQ argmin -> dec GEMM1(gather,relu)
//         -> dec GEMM2(sigmoid, writes d_out) -> loss reduction
// No dynamic smem > 48KB, no static guards, no attribute calls in launch.
// ---------------------------------------------------------------------------

#define BATCH_N   16384
#define IN_DIM    1024
#define HID_DIM   2048
#define LAT_DIM   256
#define NUM_EMB   8192

// Scratch (static device globals — no runtime allocation)
__device__ float g_H[BATCH_N * HID_DIM];     // encoder hidden
__device__ float g_Z[BATCH_N * LAT_DIM];     // latent
__device__ float g_HD[BATCH_N * HID_DIM];    // decoder hidden
__device__ int   g_idx[BATCH_N];             // argmin indices
__device__ float g_cnorm[NUM_EMB];           // ||c_k||^2
__device__ float g_partials[256];            // loss partial sums

// ---------------------------------------------------------------------------
// Codebook squared norms: one warp per code
// ---------------------------------------------------------------------------
__global__ __launch_bounds__(256) void cnorm_kernel(const float* __restrict__ CB) {
    int warp = (blockIdx.x << 3) + (threadIdx.x >> 5);
    int lane = threadIdx.x & 31;
    float s = 0.f;
    const float* row = CB + (size_t)warp * LAT_DIM;
    #pragma unroll
    for (int d = lane; d < LAT_DIM; d += 32) {
        float v = row[d];
        s += v * v;
    }
    #pragma unroll
    for (int off = 16; off > 0; off >>= 1)
        s += __shfl_xor_sync(0xFFFFFFFFu, s, off);
    if (lane == 0) g_cnorm[warp] = s;
}

// ---------------------------------------------------------------------------
// Tiled GEMM: C[M,N] = act(A[M,K] @ B[K,N] + bias)
// ACT: 0 = none, 1 = relu, 2 = sigmoid.  GATHER: A row r comes from A[gidx[r]].
// BM=BN=128, BK=16, 256 threads, 8x8 per thread.
// ---------------------------------------------------------------------------
template<int ACT, bool GATHER>
__global__ __launch_bounds__(256) void gemm_kernel(
    const float* __restrict__ A, const float* __restrict__ B,
    const float* __restrict__ bias, const int* __restrict__ gidx,
    float* __restrict__ C, int M, int N, int K)
{
    const int BM = 128, BN = 128, BK = 16;
    const int ASTR = BM + 4;   // padded row stride for As

    __shared__ float As[BK * ASTR];   // transposed: As[k][m]
    __shared__ float Bs[BK * BN];     // Bs[k][n]
    __shared__ int   sIdx[BM];

    int tid = threadIdx.x;
    int bm = blockIdx.y * BM;
    int bn = blockIdx.x * BN;

    if (GATHER) {
        if (tid < BM) sIdx[tid] = gidx[bm + tid];
        __syncthreads();
    }

    int ty = tid >> 4, tx = tid & 15;
    int row0 = ty << 3, col0 = tx << 3;

    int arow = tid >> 2;            // 0..63
    int acol = (tid & 3) << 2;      // 0,4,8,12
    int brow = tid >> 5;            // 0..7
    int bcol = (tid & 31) << 2;     // 0..124

    float acc[8][8];
    #pragma unroll
    for (int i = 0; i < 8; i++)
        #pragma unroll
        for (int j = 0; j < 8; j++) acc[i][j] = 0.f;

    for (int k0 = 0; k0 < K; k0 += BK) {
        #pragma unroll
        for (int h = 0; h < 2; h++) {
            int r = arow + h * 64;
            int grow = GATHER ? sIdx[r] : (bm + r);
            float4 v = *(const float4*)&A[(size_t)grow * K + k0 + acol];
            As[(acol + 0) * ASTR + r] = v.x;
            As[(acol + 1) * ASTR + r] = v.y;
            As[(acol + 2) * ASTR + r] = v.z;
            As[(acol + 3) * ASTR + r] = v.w;
        }
        #pragma unroll
        for (int h = 0; h < 2; h++) {
            int r = brow + h * 8;
            *(float4*)&Bs[r * BN + bcol] =
                *(const float4*)&B[(size_t)(k0 + r) * N + bn + bcol];
        }
        __syncthreads();

        #pragma unroll
        for (int k = 0; k < BK; k++) {
            float a[8], b[8];
            *(float4*)&a[0] = *(const float4*)&As[k * ASTR + row0];
            *(float4*)&a[4] = *(const float4*)&As[k * ASTR + row0 + 4];
            *(float4*)&b[0] = *(const float4*)&Bs[k * BN + col0];
            *(float4*)&b[4] = *(const float4*)&Bs[k * BN + col0 + 4];
            #pragma unroll
            for (int i = 0; i < 8; i++)
                #pragma unroll
                for (int j = 0; j < 8; j++)
                    acc[i][j] += a[i] * b[j];
        }
        __syncthreads();
    }

    float bv[8];
    *(float4*)&bv[0] = *(const float4*)&bias[bn + col0];
    *(float4*)&bv[4] = *(const float4*)&bias[bn + col0 + 4];

    #pragma unroll
    for (int i = 0; i < 8; i++) {
        int row = bm + row0 + i;
        float out[8];
        #pragma unroll
        for (int j = 0; j < 8; j++) {
            float v = acc[i][j] + bv[j];
            if (ACT == 1) v = fmaxf(v, 0.f);
            else if (ACT == 2) v = 1.f / (1.f + expf(-v));
            out[j] = v;
        }
        *(float4*)&C[(size_t)row * N + bn + col0]     = *(float4*)&out[0];
        *(float4*)&C[(size_t)row * N + bn + col0 + 4] = *(float4*)&out[4];
    }
}

// ---------------------------------------------------------------------------
// Vector quantizer: per row argmin_k (||c_k||^2 - 2 z.c_k)
// Block: 64 rows. Loops over 8192 codes in chunks of 128, K=256 staged in
// BK=16 slabs (GEMM-style). Static smem ~13KB -> multiple CTAs/SM, no
// cudaFuncSetAttribute needed, fully capture-safe.
// Per-thread micro-tile: 4 rows x 8 codes. Deterministic argmin.
// ---------------------------------------------------------------------------
#define VBM 64
#define VBN 128
#define VBK 16
#define VASTR (VBM + 4)
#define VBSTR (VBN + 4)

__global__ __launch_bounds__(256) void vq_kernel(
    const float* __restrict__ Z, const float* __restrict__ CB,
    int* __restrict__ outIdx)
{
    __shared__ float As[VBK * VASTR];   // Z tile transposed: As[k][r]
    __shared__ float Bs[VBK * VBSTR];   // code chunk transposed: Bs[k][c]

    int tid = threadIdx.x;
    int bm = blockIdx.x * VBM;

    // A-load mapping: 64 rows x 16 k per slab = 1024 floats = 1 float4/thread
    int azr = tid >> 2;             // 0..63 row
    int azk = (tid & 3) << 2;       // 0,4,8,12
    // B-load mapping: 128 codes x 16 k = 2048 floats = 2 float4/thread
    int bcr = tid >> 1;             // 0..127 code-in-chunk
    int bck = (tid & 1) << 3;       // 0 or 8

    int rg = tid & 15;              // row group
    int cg = tid >> 4;              // code group
    int r0 = rg << 2;               // 4 rows
    int c0loc = cg << 3;            // 8 codes

    float rmin[4];
    int   rid[4];
    #pragma unroll
    for (int i = 0; i < 4; i++) { rmin[i] = 3.4e38f; rid[i] = 0; }

    for (int c0 = 0; c0 < NUM_EMB; c0 += VBN) {
        float acc[4][8];
        #pragma unroll
        for (int i = 0; i < 4; i++)
            #pragma unroll
            for (int j = 0; j < 8; j++) acc[i][j] = 0.f;

        for (int k0 = 0; k0 < LAT_DIM; k0 += VBK) {
            // Z slab (transposed)
            {
                float4 v = *(const float4*)&Z[(size_t)(bm + azr) * LAT_DIM + k0 + azk];
                As[(azk + 0) * VASTR + azr] = v.x;
                As[(azk + 1) * VASTR + azr] = v.y;
                As[(azk + 2) * VASTR + azr] = v.z;
                As[(azk + 3) * VASTR + azr] = v.w;
            }
            // codebook slab (transposed)
            #pragma unroll
            for (int h = 0; h < 2; h++) {
                int k = bck + h * 4;
                float4 v = *(const float4*)&CB[(size_t)(c0 + bcr) * LAT_DIM + k0 + k];
                Bs[(k + 0) * VBSTR + bcr] = v.x;
                Bs[(k + 1) * VBSTR + bcr] = v.y;
                Bs[(k + 2) * VBSTR + bcr] = v.z;
                Bs[(k + 3) * VBSTR + bcr] = v.w;
            }
            __syncthreads();

            #pragma unroll
            for (int k = 0; k < VBK; k++) {
                float a[4], b[8];
                *(float4*)&a[0] = *(const float4*)&As[k * VASTR + r0];
                *(float4*)&b[0] = *(const float4*)&Bs[k * VBSTR + c0loc];
                *(float4*)&b[4] = *(const float4*)&Bs[k * VBSTR + c0loc + 4];
                #pragma unroll
                for (int i = 0; i < 4; i++)
                    #pragma unroll
                    for (int j = 0; j < 8; j++)
                        acc[i][j] += a[i] * b[j];
            }
            __syncthreads();
        }

        #pragma unroll
        for (int j = 0; j < 8; j++) {
            int code = c0 + c0loc + j;
            float cn = __ldg(&g_cnorm[code]);
            #pragma unroll
            for (int i = 0; i < 4; i++) {
                float s = cn - 2.f * acc[i][j];
                if (s < rmin[i]) { rmin[i] = s; rid[i] = code; }
            }
        }
    }

    // Cross-thread reduction per row (16 candidates/row)
    __shared__ float redM[VBM * 16];
    __shared__ int   redI[VBM * 16];
    #pragma unroll
    for (int i = 0; i < 4; i++) {
        redM[(r0 + i) * 16 + cg] = rmin[i];
        redI[(r0 + i) * 16 + cg] = rid[i];
    }
    __syncthreads();
    if (tid < VBM) {
        float best = 3.4e38f; int bi = 0;
        #pragma unroll
        for (int g = 0; g < 16; g++) {
            float v = redM[tid * 16 + g];
            if (v < best) { best = v; bi = redI[tid * 16 + g]; }
        }
        outIdx[bm + tid] = bi;
    }
}

// ---------------------------------------------------------------------------
// Loss: 1.25 * mean((codebook[idx] - z)^2)  — deterministic two-pass reduce
// ---------------------------------------------------------------------------
__global__ __launch_bounds__(256) void loss_partial_kernel(
    const float* __restrict__ Z, const float* __restrict__ CB,
    const int* __restrict__ idx)
{
    __shared__ float red[256];
    int tid = threadIdx.x;
    int b = blockIdx.x;                  // 256 blocks, 64 rows each
    float s = 0.f;
    for (int e = tid; e < VBM * LAT_DIM; e += 256) {
        int r = b * VBM + (e >> 8);
        int d = e & 255;
        float diff = CB[(size_t)idx[r] * LAT_DIM + d] - Z[(size_t)r * LAT_DIM + d];
        s += diff * diff;
    }
    red[tid] = s;
    __syncthreads();
    for (int st = 128; st > 0; st >>= 1) {
        if (tid < st) red[tid] += red[tid + st];
        __syncthreads();
    }
    if (tid == 0) g_partials[b] = red[0];
}

__global__ __launch_bounds__(256) void loss_final_kernel(float* __restrict__ out) {
    __shared__ float red[256];
    int tid = threadIdx.x;
    red[tid] = g_partials[tid];
    __syncthreads();
    for (int st = 128; st > 0; st >>= 1) {
        if (tid < st) red[tid] += red[tid + st];
        __syncthreads();
    }
    if (tid == 0)
        out[0] = 1.25f * red[0] / ((float)BATCH_N * (float)LAT_DIM);
}

// ---------------------------------------------------------------------------
extern "C" void kernel_launch(void* const* d_in, const int* in_sizes, int n_in,
                              void* d_out, int out_size)
{
    const float* x      = (const float*)d_in[0];
    const float* enc_w1 = (const float*)d_in[1];
    const float* enc_b1 = (const float*)d_in[2];
    const float* enc_w2 = (const float*)d_in[3];
    const float* enc_b2 = (const float*)d_in[4];
    const float* cbook  = (const float*)d_in[5];
    const float* dec_w1 = (const float*)d_in[6];
    const float* dec_b1 = (const float*)d_in[7];
    const float* dec_w2 = (const float*)d_in[8];
    const float* dec_b2 = (const float*)d_in[9];
    float* out = (float*)d_out;

    float* H;   cudaGetSymbolAddress((void**)&H,  g_H);
    float* Zp;  cudaGetSymbolAddress((void**)&Zp, g_Z);
    float* HD;  cudaGetSymbolAddress((void**)&HD, g_HD);
    int*   idx; cudaGetSymbolAddress((void**)&idx, g_idx);

    // codebook norms
    cnorm_kernel<<<NUM_EMB / 8, 256>>>(cbook);

    // encoder
    gemm_kernel<1, false><<<dim3(HID_DIM / 128, BATCH_N / 128), 256>>>(
        x, enc_w1, enc_b1, nullptr, H, BATCH_N, HID_DIM, IN_DIM);
    gemm_kernel<0, false><<<dim3(LAT_DIM / 128, BATCH_N / 128), 256>>>(
        H, enc_w2, enc_b2, nullptr, Zp, BATCH_N, LAT_DIM, HID_DIM);

    // vector quantizer
    vq_kernel<<<BATCH_N / VBM, 256>>>(Zp, cbook, idx);

    // decoder (A rows gathered from codebook by idx)
    gemm_kernel<1, true><<<dim3(HID_DIM / 128, BATCH_N / 128), 256>>>(
        cbook, dec_w1, dec_b1, idx, HD, BATCH_N, HID_DIM, LAT_DIM);
    gemm_kernel<2, false><<<dim3(IN_DIM / 128, BATCH_N / 128), 256>>>(
        HD, dec_w2, dec_b2, nullptr, out, BATCH_N, IN_DIM, HID_DIM);

    // loss scalar -> last output element
    loss_partial_kernel<<<BATCH_N / VBM, 256>>>(Zp, cbook, idx);
    loss_final_kernel<<<1, 256>>>(out + (size_t)BATCH_N * IN_DIM);
}

// round 5
// speedup vs baseline: 2.2397x; 2.2397x over previous
#include <cuda_runtime.h>
#include <cuda_bf16.h>
#include <math.h>

// ===========================================================================
// VQ-VAE forward on GB300 (sm_103 base target) — mma.sync bf16 split-precision
// tcgen05 is NOT available in this toolchain (ptxas targets sm_103 without 'a')
// so tensor work goes through baseline m16n8k16 HMMA + ldmatrix + cp.async.
// ===========================================================================

#define BATCH_N 16384
#define IN_DIM  1024
#define HID_DIM 2048
#define LAT_DIM 256
#define NUM_EMB 8192
#define NT_VQ   (NUM_EMB / 128)

// ---------------- static device scratch ----------------
__device__ __nv_bfloat16 g_Xh[BATCH_N * IN_DIM],  g_Xl[BATCH_N * IN_DIM];
__device__ __nv_bfloat16 g_Hh[BATCH_N * HID_DIM], g_Hl[BATCH_N * HID_DIM];
__device__ __nv_bfloat16 g_Zh[BATCH_N * LAT_DIM], g_Zl[BATCH_N * LAT_DIM];
__device__ __nv_bfloat16 g_HDh[BATCH_N * HID_DIM], g_HDl[BATCH_N * HID_DIM];
__device__ __nv_bfloat16 g_W1h[HID_DIM * IN_DIM],  g_W1l[HID_DIM * IN_DIM];
__device__ __nv_bfloat16 g_W2h[LAT_DIM * HID_DIM], g_W2l[LAT_DIM * HID_DIM];
__device__ __nv_bfloat16 g_D1h[HID_DIM * LAT_DIM], g_D1l[HID_DIM * LAT_DIM];
__device__ __nv_bfloat16 g_D2h[IN_DIM * HID_DIM],  g_D2l[IN_DIM * HID_DIM];
__device__ __nv_bfloat16 g_CBh[NUM_EMB * LAT_DIM], g_CBl[NUM_EMB * LAT_DIM];
__device__ float g_cnorm[NUM_EMB];
__device__ float g_candV[BATCH_N * NT_VQ];
__device__ int   g_candI[BATCH_N * NT_VQ];
__device__ int   g_idx[BATCH_N];
__device__ float g_partials[256];

// ---------------- helpers ----------------
__device__ __forceinline__ unsigned smem_u32(const void* p) {
    unsigned a;
    asm("{ .reg .u64 t; cvta.to.shared.u64 t, %1; cvt.u32.u64 %0, t; }" : "=r"(a) : "l"(p));
    return a;
}
#define CP_ASYNC16(dst, src) \
    asm volatile("cp.async.cg.shared.global [%0], [%1], 16;" :: "r"(dst), "l"(src))
#define CP_COMMIT() asm volatile("cp.async.commit_group;" ::: "memory")
#define CP_WAIT1()  asm volatile("cp.async.wait_group 1;" ::: "memory")
#define CP_WAIT0()  asm volatile("cp.async.wait_group 0;" ::: "memory")

__device__ __forceinline__ uint4 ldsm4(unsigned addr) {
    uint4 r;
    asm volatile("ldmatrix.sync.aligned.m8n8.x4.shared.b16 {%0,%1,%2,%3}, [%4];"
                 : "=r"(r.x), "=r"(r.y), "=r"(r.z), "=r"(r.w) : "r"(addr));
    return r;
}
__device__ __forceinline__ void mma16816(float* c, const uint4& a, const uint2& b) {
    asm volatile("mma.sync.aligned.m16n8k16.row.col.f32.bf16.bf16.f32 "
                 "{%0,%1,%2,%3}, {%4,%5,%6,%7}, {%8,%9}, {%0,%1,%2,%3};"
                 : "+f"(c[0]), "+f"(c[1]), "+f"(c[2]), "+f"(c[3])
                 : "r"(a.x), "r"(a.y), "r"(a.z), "r"(a.w), "r"(b.x), "r"(b.y));
}
__device__ __forceinline__ unsigned pk_split(float v) {
    __nv_bfloat16 h = __float2bfloat16(v);
    float r = v - __bfloat162float(h);
    return ((unsigned)__bfloat16_as_ushort(h) << 16) |
           (unsigned)__bfloat16_as_ushort(__float2bfloat16(r));
}
__device__ __forceinline__ unsigned hi2(float a, float b) {   // bf16x2 of hi parts
    unsigned pa = pk_split(a), pb = pk_split(b);
    return __byte_perm(pa, pb, 0x7632);
}
__device__ __forceinline__ unsigned lo2(float a, float b) {   // bf16x2 of lo parts
    unsigned pa = pk_split(a), pb = pk_split(b);
    return __byte_perm(pa, pb, 0x5410);
}

// ---------------- prep kernels ----------------
// W[K][N] fp32 -> transposed hi/lo bf16 [N][K]
__global__ __launch_bounds__(256) void wsplit_t(const float* __restrict__ W,
                                                __nv_bfloat16* __restrict__ Th,
                                                __nv_bfloat16* __restrict__ Tl,
                                                int K, int N) {
    __shared__ float t[32][33];
    int k0 = blockIdx.y * 32, n0 = blockIdx.x * 32;
    int tx = threadIdx.x, ty = threadIdx.y;
    #pragma unroll
    for (int i = 0; i < 4; i++) {
        int r = ty + 8 * i;
        t[r][tx] = W[(size_t)(k0 + r) * N + n0 + tx];
    }
    __syncthreads();
    #pragma unroll
    for (int i = 0; i < 4; i++) {
        int r = ty + 8 * i;
        float v = t[tx][r];
        __nv_bfloat16 h = __float2bfloat16(v);
        Th[(size_t)(n0 + r) * K + k0 + tx] = h;
        Tl[(size_t)(n0 + r) * K + k0 + tx] = __float2bfloat16(v - __bfloat162float(h));
    }
}

// fp32 array -> separate hi/lo bf16 arrays (layout preserved)
__global__ __launch_bounds__(256) void split2_k(const float4* __restrict__ in,
                                                uint2* __restrict__ oh,
                                                uint2* __restrict__ ol, int n4) {
    int i = blockIdx.x * 256 + threadIdx.x;
    if (i < n4) {
        float4 v = in[i];
        oh[i] = make_uint2(hi2(v.x, v.y), hi2(v.z, v.w));
        ol[i] = make_uint2(lo2(v.x, v.y), lo2(v.z, v.w));
    }
}

__global__ __launch_bounds__(256) void cnorm_kernel(const float* __restrict__ CB) {
    int code = (blockIdx.x << 3) + (threadIdx.x >> 5);
    int lane = threadIdx.x & 31;
    float s = 0.f;
    const float* row = CB + (size_t)code * LAT_DIM;
    #pragma unroll
    for (int d = lane; d < LAT_DIM; d += 32) { float v = row[d]; s += v * v; }
    #pragma unroll
    for (int off = 16; off > 0; off >>= 1) s += __shfl_xor_sync(0xFFFFFFFFu, s, off);
    if (lane == 0) g_cnorm[code] = s;
}

// ---------------------------------------------------------------------------
// mma.sync GEMM: 128x128 tile, BK=32, 8 warps (2x4), warp tile 64x32,
// 2-stage cp.async double buffer, 80B padded smem rows (ldmatrix conflict-free).
// Split precision: acc += Ah*Bh + Al*Bh + Ah*Bl  (fp32 accumulate).
// A: [M][K] bf16 hi/lo (optionally row-gathered). B: [N][K] bf16 hi/lo.
// ---------------------------------------------------------------------------
#define ROWB    80
#define ARR_B   (128 * ROWB)        // 10240 per array
#define STAGE_B (4 * ARR_B)         // 40960 per stage (Ah, Al, Bh, Bl)
#define RED_OFF (2 * STAGE_B)       // argmin scratch
#define IDX_OFF (RED_OFF + 4096)
#define SMEM_DYN (IDX_OFF + 512)

enum { EPI_RELU = 0, EPI_PACK = 1, EPI_SIG = 2, EPI_ARGMIN = 3 };

template<bool GATHER, int EPI>
__global__ __launch_bounds__(256, 1)
void mm_kernel(const __nv_bfloat16* __restrict__ Ah, const __nv_bfloat16* __restrict__ Al,
               const int* __restrict__ gidx,
               const __nv_bfloat16* __restrict__ Bh, const __nv_bfloat16* __restrict__ Bl,
               const float* __restrict__ bias,
               __nv_bfloat16* __restrict__ outH, __nv_bfloat16* __restrict__ outL,
               float* __restrict__ outF,
               float* __restrict__ candV, int* __restrict__ candI,
               const float* __restrict__ cnorm,
               int K, int N)
{
    extern __shared__ __align__(16) char dsm[];
    unsigned su = smem_u32(dsm);
    float* redV = (float*)(dsm + RED_OFF);            // [128][4]
    int*   redI = (int*)(dsm + RED_OFF + 2048);       // [128][4]
    int*   sIdx = (int*)(dsm + IDX_OFF);

    int tid = threadIdx.x;
    int lane = tid & 31;
    int warp = tid >> 5;
    int warpM = warp >> 2, warpN = warp & 3;          // 2 x 4
    int m0 = blockIdx.y * 128;
    int n0 = blockIdx.x * 128;

    if (GATHER) {
        if (tid < 128) sIdx[tid] = gidx[m0 + tid];
        __syncthreads();
    }

    // loader mapping: 2048 x 16B chunks per stage, 8 per thread
    // u = tid + 256*j : arr=u>>9 (0 Ah,1 Al,2 Bh,3 Bl), row=(u&511)>>2, ch=u&3
    float acc[4][4][4];
    #pragma unroll
    for (int i = 0; i < 4; i++)
        #pragma unroll
        for (int j = 0; j < 4; j++)
            #pragma unroll
            for (int q = 0; q < 4; q++) acc[i][j][q] = 0.f;

    int S = K >> 5;

    // ---- stage loader (lambda-free for nvcc friendliness) ----
    #define LOAD_STAGE(stg, k0v)                                               \
    {                                                                          \
        int k0_ = (k0v);                                                       \
        _Pragma("unroll")                                                      \
        for (int j = 0; j < 8; j++) {                                          \
            int u = tid + 256 * j;                                             \
            int arr = u >> 9, v = u & 511, row = v >> 2, ch = v & 3;           \
            const __nv_bfloat16* src;                                          \
            int rg;                                                            \
            if (arr & 2) { rg = n0 + row; src = (arr & 1) ? Bl : Bh; }         \
            else {                                                             \
                rg = GATHER ? sIdx[row] : (m0 + row);                          \
                src = (arr & 1) ? Al : Ah;                                     \
            }                                                                  \
            src += (size_t)rg * K + k0_ + ch * 8;                              \
            unsigned dst = su + (stg) * STAGE_B + arr * ARR_B + row * ROWB + ch * 16; \
            CP_ASYNC16(dst, src);                                              \
        }                                                                      \
        CP_COMMIT();                                                           \
    }

    LOAD_STAGE(0, 0);

    for (int s = 0; s < S; s++) {
        if (s + 1 < S) LOAD_STAGE((s + 1) & 1, (s + 1) << 5);
        if (s + 1 < S) { CP_WAIT1(); } else { CP_WAIT0(); }
        __syncthreads();

        unsigned sb = su + (s & 1) * STAGE_B;
        int lt = lane >> 3, lr = lane & 7;
        #pragma unroll
        for (int kk = 0; kk < 32; kk += 16) {
            uint4 ah[4], al[4];
            uint2 bh[4], bl[4];
            #pragma unroll
            for (int mf = 0; mf < 4; mf++) {
                int mrow = warpM * 64 + mf * 16 + (lt & 1) * 8 + lr;
                unsigned kb = (kk + (lt >> 1) * 8) * 2;
                ah[mf] = ldsm4(sb + 0 * ARR_B + mrow * ROWB + kb);
                al[mf] = ldsm4(sb + 1 * ARR_B + mrow * ROWB + kb);
            }
            #pragma unroll
            for (int nf2 = 0; nf2 < 2; nf2++) {
                int nrow = warpN * 32 + nf2 * 16 + (lt >> 1) * 8 + lr;
                unsigned kb = (kk + (lt & 1) * 8) * 2;
                uint4 h4 = ldsm4(sb + 2 * ARR_B + nrow * ROWB + kb);
                uint4 l4 = ldsm4(sb + 3 * ARR_B + nrow * ROWB + kb);
                bh[2 * nf2]     = make_uint2(h4.x, h4.y);
                bh[2 * nf2 + 1] = make_uint2(h4.z, h4.w);
                bl[2 * nf2]     = make_uint2(l4.x, l4.y);
                bl[2 * nf2 + 1] = make_uint2(l4.z, l4.w);
            }
            #pragma unroll
            for (int mf = 0; mf < 4; mf++)
                #pragma unroll
                for (int nf = 0; nf < 4; nf++) {
                    mma16816(acc[mf][nf], ah[mf], bh[nf]);
                    mma16816(acc[mf][nf], al[mf], bh[nf]);
                    mma16816(acc[mf][nf], ah[mf], bl[nf]);
                }
        }
        __syncthreads();
    }

    // -------------------- epilogue --------------------
    int qr = lane >> 2;            // 0..7  (row within 8)
    int qc = (lane & 3) * 2;       // 0,2,4,6

    if (EPI == EPI_ARGMIN) {
        // per-thread: 8 m-rows (mf x half), min over its 8 n's
        #pragma unroll
        for (int mf = 0; mf < 4; mf++) {
            #pragma unroll
            for (int h = 0; h < 2; h++) {
                int mloc = warpM * 64 + mf * 16 + h * 8 + qr;
                float bv = 3.4e38f; int bi = 0;
                #pragma unroll
                for (int nf = 0; nf < 4; nf++) {
                    #pragma unroll
                    for (int p = 0; p < 2; p++) {
                        int n = n0 + warpN * 32 + nf * 8 + qc + p;
                        float sc = cnorm[n] - 2.f * acc[mf][nf][2 * h + p];
                        if (sc < bv || (sc == bv && n < bi)) { bv = sc; bi = n; }
                    }
                }
                // quad reduce (lanes sharing qr)
                #pragma unroll
                for (int x = 1; x < 4; x <<= 1) {
                    float v2 = __shfl_xor_sync(0xFFFFFFFFu, bv, x);
                    int   i2 = __shfl_xor_sync(0xFFFFFFFFu, bi, x);
                    if (v2 < bv || (v2 == bv && i2 < bi)) { bv = v2; bi = i2; }
                }
                if ((lane & 3) == 0) {
                    redV[mloc * 4 + warpN] = bv;
                    redI[mloc * 4 + warpN] = bi;
                }
            }
        }
        __syncthreads();
        if (tid < 128) {
            float bv = 3.4e38f; int bi = 0;
            #pragma unroll
            for (int wq = 0; wq < 4; wq++) {
                float v = redV[tid * 4 + wq];
                int   i = redI[tid * 4 + wq];
                if (v < bv || (v == bv && i < bi)) { bv = v; bi = i; }
            }
            candV[(size_t)(m0 + tid) * NT_VQ + blockIdx.x] = bv;
            candI[(size_t)(m0 + tid) * NT_VQ + blockIdx.x] = bi;
        }
    } else {
        #pragma unroll
        for (int mf = 0; mf < 4; mf++) {
            #pragma unroll
            for (int h = 0; h < 2; h++) {
                int gm = m0 + warpM * 64 + mf * 16 + h * 8 + qr;
                #pragma unroll
                for (int nf = 0; nf < 4; nf++) {
                    int n = n0 + warpN * 32 + nf * 8 + qc;
                    float v0 = acc[mf][nf][2 * h + 0] + bias[n];
                    float v1 = acc[mf][nf][2 * h + 1] + bias[n + 1];
                    if (EPI == EPI_RELU) { v0 = fmaxf(v0, 0.f); v1 = fmaxf(v1, 0.f); }
                    size_t off = (size_t)gm * N + n;
                    if (EPI == EPI_SIG) {
                        v0 = 1.f / (1.f + __expf(-v0));
                        v1 = 1.f / (1.f + __expf(-v1));
                        *(float2*)(outF + off) = make_float2(v0, v1);
                    } else {
                        *(unsigned*)(outH + off) = hi2(v0, v1);
                        *(unsigned*)(outL + off) = lo2(v0, v1);
                    }
                }
            }
        }
    }
    #undef LOAD_STAGE
}

// per-row argmin over the NT_VQ column-tile candidates
__global__ __launch_bounds__(256) void vqred_k() {
    int r = blockIdx.x * 256 + threadIdx.x;
    const float* cv = g_candV + (size_t)r * NT_VQ;
    const int*   ci = g_candI + (size_t)r * NT_VQ;
    float best = 3.4e38f; int bi = 0;
    #pragma unroll
    for (int t = 0; t < NT_VQ; t++) {
        float v = cv[t]; int i = ci[t];
        if (v < best || (v == best && i < bi)) { best = v; bi = i; }
    }
    g_idx[r] = bi;
}

// loss = 1.25 * mean((codebook[idx] - z)^2), z reconstructed from hi+lo
__global__ __launch_bounds__(256) void loss_partial_kernel(const float* __restrict__ CB) {
    __shared__ float red[256];
    int tid = threadIdx.x;
    int b = blockIdx.x;
    float s = 0.f;
    for (int e = tid; e < 64 * LAT_DIM; e += 256) {
        int r = b * 64 + (e >> 8);
        int d = e & 255;
        size_t o = (size_t)r * LAT_DIM + d;
        float z = __bfloat162float(g_Zh[o]) + __bfloat162float(g_Zl[o]);
        float diff = CB[(size_t)g_idx[r] * LAT_DIM + d] - z;
        s += diff * diff;
    }
    red[tid] = s;
    __syncthreads();
    for (int st = 128; st > 0; st >>= 1) {
        if (tid < st) red[tid] += red[tid + st];
        __syncthreads();
    }
    if (tid == 0) g_partials[b] = red[0];
}

__global__ __launch_bounds__(256) void loss_final_kernel(float* __restrict__ out) {
    __shared__ float red[256];
    int tid = threadIdx.x;
    red[tid] = g_partials[tid];
    __syncthreads();
    for (int st = 128; st > 0; st >>= 1) {
        if (tid < st) red[tid] += red[tid + st];
        __syncthreads();
    }
    if (tid == 0) out[0] = 1.25f * red[0] / ((float)BATCH_N * (float)LAT_DIM);
}

// ---------------------------------------------------------------------------
extern "C" void kernel_launch(void* const* d_in, const int* in_sizes, int n_in,
                              void* d_out, int out_size)
{
    (void)in_sizes; (void)n_in; (void)out_size;
    const float* x      = (const float*)d_in[0];
    const float* enc_w1 = (const float*)d_in[1];
    const float* enc_b1 = (const float*)d_in[2];
    const float* enc_w2 = (const float*)d_in[3];
    const float* enc_b2 = (const float*)d_in[4];
    const float* cbook  = (const float*)d_in[5];
    const float* dec_w1 = (const float*)d_in[6];
    const float* dec_b1 = (const float*)d_in[7];
    const float* dec_w2 = (const float*)d_in[8];
    const float* dec_b2 = (const float*)d_in[9];
    float* out = (float*)d_out;

    cudaFuncSetAttribute(mm_kernel<false, EPI_RELU>,
                         cudaFuncAttributeMaxDynamicSharedMemorySize, SMEM_DYN);
    cudaFuncSetAttribute(mm_kernel<false, EPI_PACK>,
                         cudaFuncAttributeMaxDynamicSharedMemorySize, SMEM_DYN);
    cudaFuncSetAttribute(mm_kernel<false, EPI_ARGMIN>,
                         cudaFuncAttributeMaxDynamicSharedMemorySize, SMEM_DYN);
    cudaFuncSetAttribute(mm_kernel<true,  EPI_RELU>,
                         cudaFuncAttributeMaxDynamicSharedMemorySize, SMEM_DYN);
    cudaFuncSetAttribute(mm_kernel<false, EPI_SIG>,
                         cudaFuncAttributeMaxDynamicSharedMemorySize, SMEM_DYN);

    __nv_bfloat16 *Xh, *Xl, *Hh, *Hl, *Zh, *Zl, *HDh, *HDl;
    __nv_bfloat16 *W1h, *W1l, *W2h, *W2l, *D1h, *D1l, *D2h, *D2l, *CBh, *CBl;
    float *candV, *cnorm; int *candI, *idx;
    cudaGetSymbolAddress((void**)&Xh,  g_Xh);  cudaGetSymbolAddress((void**)&Xl,  g_Xl);
    cudaGetSymbolAddress((void**)&Hh,  g_Hh);  cudaGetSymbolAddress((void**)&Hl,  g_Hl);
    cudaGetSymbolAddress((void**)&Zh,  g_Zh);  cudaGetSymbolAddress((void**)&Zl,  g_Zl);
    cudaGetSymbolAddress((void**)&HDh, g_HDh); cudaGetSymbolAddress((void**)&HDl, g_HDl);
    cudaGetSymbolAddress((void**)&W1h, g_W1h); cudaGetSymbolAddress((void**)&W1l, g_W1l);
    cudaGetSymbolAddress((void**)&W2h, g_W2h); cudaGetSymbolAddress((void**)&W2l, g_W2l);
    cudaGetSymbolAddress((void**)&D1h, g_D1h); cudaGetSymbolAddress((void**)&D1l, g_D1l);
    cudaGetSymbolAddress((void**)&D2h, g_D2h); cudaGetSymbolAddress((void**)&D2l, g_D2l);
    cudaGetSymbolAddress((void**)&CBh, g_CBh); cudaGetSymbolAddress((void**)&CBl, g_CBl);
    cudaGetSymbolAddress((void**)&candV, g_candV);
    cudaGetSymbolAddress((void**)&candI, g_candI);
    cudaGetSymbolAddress((void**)&cnorm, g_cnorm);
    cudaGetSymbolAddress((void**)&idx,   g_idx);

    dim3 tb(32, 8);
    wsplit_t<<<dim3(HID_DIM / 32, IN_DIM / 32),  tb>>>(enc_w1, W1h, W1l, IN_DIM,  HID_DIM);
    wsplit_t<<<dim3(LAT_DIM / 32, HID_DIM / 32), tb>>>(enc_w2, W2h, W2l, HID_DIM, LAT_DIM);
    wsplit_t<<<dim3(HID_DIM / 32, LAT_DIM / 32), tb>>>(dec_w1, D1h, D1l, LAT_DIM, HID_DIM);
    wsplit_t<<<dim3(IN_DIM / 32,  HID_DIM / 32), tb>>>(dec_w2, D2h, D2l, HID_DIM, IN_DIM);
    split2_k<<<(NUM_EMB * LAT_DIM / 4) / 256, 256>>>(
        (const float4*)cbook, (uint2*)CBh, (uint2*)CBl, NUM_EMB * LAT_DIM / 4);
    split2_k<<<(BATCH_N * IN_DIM / 4) / 256, 256>>>(
        (const float4*)x, (uint2*)Xh, (uint2*)Xl, BATCH_N * IN_DIM / 4);
    cnorm_kernel<<<NUM_EMB / 8, 256>>>(cbook);

    // encoder
    mm_kernel<false, EPI_RELU><<<dim3(HID_DIM / 128, BATCH_N / 128), 256, SMEM_DYN>>>(
        Xh, Xl, nullptr, W1h, W1l, enc_b1, Hh, Hl, nullptr,
        nullptr, nullptr, nullptr, IN_DIM, HID_DIM);
    mm_kernel<false, EPI_PACK><<<dim3(LAT_DIM / 128, BATCH_N / 128), 256, SMEM_DYN>>>(
        Hh, Hl, nullptr, W2h, W2l, enc_b2, Zh, Zl, nullptr,
        nullptr, nullptr, nullptr, HID_DIM, LAT_DIM);

    // vector quantizer
    mm_kernel<false, EPI_ARGMIN><<<dim3(NUM_EMB / 128, BATCH_N / 128), 256, SMEM_DYN>>>(
        Zh, Zl, nullptr, CBh, CBl, nullptr, nullptr, nullptr, nullptr,
        candV, candI, cnorm, LAT_DIM, NUM_EMB);
    vqred_k<<<BATCH_N / 256, 256>>>();

    // decoder (A = codebook rows gathered by idx)
    mm_kernel<true, EPI_RELU><<<dim3(HID_DIM / 128, BATCH_N / 128), 256, SMEM_DYN>>>(
        CBh, CBl, idx, D1h, D1l, dec_b1, HDh, HDl, nullptr,
        nullptr, nullptr, nullptr, LAT_DIM, HID_DIM);
    mm_kernel<false, EPI_SIG><<<dim3(IN_DIM / 128, BATCH_N / 128), 256, SMEM_DYN>>>(
        HDh, HDl, nullptr, D2h, D2l, dec_b2, nullptr, nullptr, out,
        nullptr, nullptr, nullptr, HID_DIM, IN_DIM);

    // loss scalar -> last output element
    loss_partial_kernel<<<BATCH_N / 64, 256>>>(cbook);
    loss_final_kernel<<<1, 256>>>(out + (size_t)BATCH_N * IN_DIM);
}

// round 8
// speedup vs baseline: 3.1527x; 1.4076x over previous
#include <cuda_runtime.h>
#include <cuda_bf16.h>
#include <cuda_fp16.h>
#include <math.h>

// ===========================================================================
// VQ-VAE forward (sm_103 base target) — mma.sync mixed precision
//   enc1, enc2 : bf16 split 3-MMA  (z-path needs 2^-17 for the loss scalar)
//   VQ, dec1, dec2 : fp16 single-MMA (argmin gaps ~2e-4; decoder bias-dominated)
// ===========================================================================

#define BATCH_N 16384
#define IN_DIM  1024
#define HID_DIM 2048
#define LAT_DIM 256
#define NUM_EMB 8192
#define NT_VQ   (NUM_EMB / 128)
#define CB_SCALE 1024.0f            // codebook prescale (avoid fp16 subnormals)

// ---------------- static device scratch ----------------
__device__ __nv_bfloat16 g_Xh[BATCH_N * IN_DIM],  g_Xl[BATCH_N * IN_DIM];
__device__ __nv_bfloat16 g_Hh[BATCH_N * HID_DIM], g_Hl[BATCH_N * HID_DIM];
__device__ __nv_bfloat16 g_Zh[BATCH_N * LAT_DIM], g_Zl[BATCH_N * LAT_DIM];
__device__ __half        g_Zf[BATCH_N * LAT_DIM];       // z fp16 (VQ A)
__device__ __half        g_HDf[BATCH_N * HID_DIM];      // decoder hidden fp16
__device__ __nv_bfloat16 g_W1h[HID_DIM * IN_DIM],  g_W1l[HID_DIM * IN_DIM];
__device__ __nv_bfloat16 g_W2h[LAT_DIM * HID_DIM], g_W2l[LAT_DIM * HID_DIM];
__device__ __half        g_D1f[HID_DIM * LAT_DIM];      // dec_w1^T fp16
__device__ __half        g_D2f[IN_DIM * HID_DIM];       // dec_w2^T fp16
__device__ __half        g_CBf[NUM_EMB * LAT_DIM];      // codebook * 1024, fp16
__device__ float g_cnorm[NUM_EMB];
__device__ float g_candV[BATCH_N * NT_VQ];
__device__ int   g_candI[BATCH_N * NT_VQ];
__device__ int   g_idx[BATCH_N];
__device__ float g_partials[256];

// ---------------- helpers ----------------
__device__ __forceinline__ unsigned smem_u32(const void* p) {
    unsigned a;
    asm("{ .reg .u64 t; cvta.to.shared.u64 t, %1; cvt.u32.u64 %0, t; }" : "=r"(a) : "l"(p));
    return a;
}
#define CP_ASYNC16(dst, src) \
    asm volatile("cp.async.cg.shared.global [%0], [%1], 16;" :: "r"(dst), "l"(src))
#define CP_COMMIT() asm volatile("cp.async.commit_group;" ::: "memory")
#define CP_WAIT1()  asm volatile("cp.async.wait_group 1;" ::: "memory")
#define CP_WAIT0()  asm volatile("cp.async.wait_group 0;" ::: "memory")

__device__ __forceinline__ uint4 ldsm4(unsigned addr) {
    uint4 r;
    asm volatile("ldmatrix.sync.aligned.m8n8.x4.shared.b16 {%0,%1,%2,%3}, [%4];"
                 : "=r"(r.x), "=r"(r.y), "=r"(r.z), "=r"(r.w) : "r"(addr));
    return r;
}
__device__ __forceinline__ void mma_bf(float* c, const uint4& a, const uint2& b) {
    asm volatile("mma.sync.aligned.m16n8k16.row.col.f32.bf16.bf16.f32 "
                 "{%0,%1,%2,%3}, {%4,%5,%6,%7}, {%8,%9}, {%0,%1,%2,%3};"
                 : "+f"(c[0]), "+f"(c[1]), "+f"(c[2]), "+f"(c[3])
                 : "r"(a.x), "r"(a.y), "r"(a.z), "r"(a.w), "r"(b.x), "r"(b.y));
}
__device__ __forceinline__ void mma_hf(float* c, const uint4& a, const uint2& b) {
    asm volatile("mma.sync.aligned.m16n8k16.row.col.f32.f16.f16.f32 "
                 "{%0,%1,%2,%3}, {%4,%5,%6,%7}, {%8,%9}, {%0,%1,%2,%3};"
                 : "+f"(c[0]), "+f"(c[1]), "+f"(c[2]), "+f"(c[3])
                 : "r"(a.x), "r"(a.y), "r"(a.z), "r"(a.w), "r"(b.x), "r"(b.y));
}
__device__ __forceinline__ unsigned pk_split(float v) {
    __nv_bfloat16 h = __float2bfloat16(v);
    float r = v - __bfloat162float(h);
    return ((unsigned)__bfloat16_as_ushort(h) << 16) |
           (unsigned)__bfloat16_as_ushort(__float2bfloat16(r));
}
__device__ __forceinline__ unsigned hi2(float a, float b) {
    unsigned pa = pk_split(a), pb = pk_split(b);
    return __byte_perm(pa, pb, 0x7632);
}
__device__ __forceinline__ unsigned lo2(float a, float b) {
    unsigned pa = pk_split(a), pb = pk_split(b);
    return __byte_perm(pa, pb, 0x5410);
}
__device__ __forceinline__ unsigned f16x2(float a, float b) {
    return (unsigned)__half_as_ushort(__float2half(a)) |
           ((unsigned)__half_as_ushort(__float2half(b)) << 16);
}

// ---------------- prep kernels ----------------
__global__ __launch_bounds__(256) void wsplit_t(const float* __restrict__ W,
                                                __nv_bfloat16* __restrict__ Th,
                                                __nv_bfloat16* __restrict__ Tl,
                                                int K, int N) {
    __shared__ float t[32][33];
    int k0 = blockIdx.y * 32, n0 = blockIdx.x * 32;
    int tx = threadIdx.x, ty = threadIdx.y;
    #pragma unroll
    for (int i = 0; i < 4; i++) {
        int r = ty + 8 * i;
        t[r][tx] = W[(size_t)(k0 + r) * N + n0 + tx];
    }
    __syncthreads();
    #pragma unroll
    for (int i = 0; i < 4; i++) {
        int r = ty + 8 * i;
        float v = t[tx][r];
        __nv_bfloat16 h = __float2bfloat16(v);
        Th[(size_t)(n0 + r) * K + k0 + tx] = h;
        Tl[(size_t)(n0 + r) * K + k0 + tx] = __float2bfloat16(v - __bfloat162float(h));
    }
}

// W[K][N] fp32 -> transposed fp16 [N][K]
__global__ __launch_bounds__(256) void wsingle_t(const float* __restrict__ W,
                                                 __half* __restrict__ T,
                                                 int K, int N) {
    __shared__ float t[32][33];
    int k0 = blockIdx.y * 32, n0 = blockIdx.x * 32;
    int tx = threadIdx.x, ty = threadIdx.y;
    #pragma unroll
    for (int i = 0; i < 4; i++) {
        int r = ty + 8 * i;
        t[r][tx] = W[(size_t)(k0 + r) * N + n0 + tx];
    }
    __syncthreads();
    #pragma unroll
    for (int i = 0; i < 4; i++) {
        int r = ty + 8 * i;
        T[(size_t)(n0 + r) * K + k0 + tx] = __float2half(t[tx][r]);
    }
}

__global__ __launch_bounds__(256) void split2_k(const float4* __restrict__ in,
                                                uint2* __restrict__ oh,
                                                uint2* __restrict__ ol, int n4) {
    int i = blockIdx.x * 256 + threadIdx.x;
    if (i < n4) {
        float4 v = in[i];
        oh[i] = make_uint2(hi2(v.x, v.y), hi2(v.z, v.w));
        ol[i] = make_uint2(lo2(v.x, v.y), lo2(v.z, v.w));
    }
}

// codebook fp32 -> fp16 scaled by CB_SCALE (layout preserved)
__global__ __launch_bounds__(256) void cbf_k(const float4* __restrict__ in,
                                             uint2* __restrict__ of, int n4) {
    int i = blockIdx.x * 256 + threadIdx.x;
    if (i < n4) {
        float4 v = in[i];
        of[i] = make_uint2(f16x2(v.x * CB_SCALE, v.y * CB_SCALE),
                           f16x2(v.z * CB_SCALE, v.w * CB_SCALE));
    }
}

__global__ __launch_bounds__(256) void cnorm_kernel(const float* __restrict__ CB) {
    int code = (blockIdx.x << 3) + (threadIdx.x >> 5);
    int lane = threadIdx.x & 31;
    float s = 0.f;
    const float* row = CB + (size_t)code * LAT_DIM;
    #pragma unroll
    for (int d = lane; d < LAT_DIM; d += 32) { float v = row[d]; s += v * v; }
    #pragma unroll
    for (int off = 16; off > 0; off >>= 1) s += __shfl_xor_sync(0xFFFFFFFFu, s, off);
    if (lane == 0) g_cnorm[code] = s;
}

// ---------------------------------------------------------------------------
// Shared geometry: 128x128 tile, BK=32, 8 warps (2x4), warp tile 64x32,
// 2-stage cp.async, 80B padded smem rows.
// ---------------------------------------------------------------------------
#define ROWB    80
#define ARR_B   (128 * ROWB)

// ---- bf16 split 3-MMA kernel (z-path) ----
#define STAGE_B  (4 * ARR_B)
#define RED_OFF  (2 * STAGE_B)
#define IDX_OFF  (RED_OFF + 4096)
#define SMEM_DYN (IDX_OFF + 512)

enum { EPI_RELU = 0, EPI_PACKZ = 1 };

template<int EPI>
__global__ __launch_bounds__(256, 1)
void mm3_kernel(const __nv_bfloat16* __restrict__ Ah, const __nv_bfloat16* __restrict__ Al,
                const __nv_bfloat16* __restrict__ Bh, const __nv_bfloat16* __restrict__ Bl,
                const float* __restrict__ bias,
                __nv_bfloat16* __restrict__ outH, __nv_bfloat16* __restrict__ outL,
                __half* __restrict__ outF16,
                int K, int N)
{
    extern __shared__ __align__(16) char dsm[];
    unsigned su = smem_u32(dsm);

    int tid = threadIdx.x;
    int lane = tid & 31;
    int warp = tid >> 5;
    int warpM = warp >> 2, warpN = warp & 3;
    int m0 = blockIdx.y * 128;
    int n0 = blockIdx.x * 128;

    float acc[4][4][4];
    #pragma unroll
    for (int i = 0; i < 4; i++)
        #pragma unroll
        for (int j = 0; j < 4; j++)
            #pragma unroll
            for (int q = 0; q < 4; q++) acc[i][j][q] = 0.f;

    int S = K >> 5;

    #define LOAD3(stg, k0v)                                                    \
    {                                                                          \
        int k0_ = (k0v);                                                       \
        _Pragma("unroll")                                                      \
        for (int j = 0; j < 8; j++) {                                          \
            int u = tid + 256 * j;                                             \
            int arr = u >> 9, v = u & 511, row = v >> 2, ch = v & 3;           \
            const __nv_bfloat16* src;                                          \
            int rg;                                                            \
            if (arr & 2) { rg = n0 + row; src = (arr & 1) ? Bl : Bh; }         \
            else         { rg = m0 + row; src = (arr & 1) ? Al : Ah; }         \
            src += (size_t)rg * K + k0_ + ch * 8;                              \
            unsigned dst = su + (stg) * STAGE_B + arr * ARR_B + row * ROWB + ch * 16; \
            CP_ASYNC16(dst, src);                                              \
        }                                                                      \
        CP_COMMIT();                                                           \
    }

    LOAD3(0, 0);
    for (int s = 0; s < S; s++) {
        if (s + 1 < S) LOAD3((s + 1) & 1, (s + 1) << 5);
        if (s + 1 < S) { CP_WAIT1(); } else { CP_WAIT0(); }
        __syncthreads();

        unsigned sb = su + (s & 1) * STAGE_B;
        int lt = lane >> 3, lr = lane & 7;
        #pragma unroll
        for (int kk = 0; kk < 32; kk += 16) {
            uint4 ah[4], al[4];
            uint2 bh[4], bl[4];
            #pragma unroll
            for (int mf = 0; mf < 4; mf++) {
                int mrow = warpM * 64 + mf * 16 + (lt & 1) * 8 + lr;
                unsigned kb = (kk + (lt >> 1) * 8) * 2;
                ah[mf] = ldsm4(sb + 0 * ARR_B + mrow * ROWB + kb);
                al[mf] = ldsm4(sb + 1 * ARR_B + mrow * ROWB + kb);
            }
            #pragma unroll
            for (int nf2 = 0; nf2 < 2; nf2++) {
                int nrow = warpN * 32 + nf2 * 16 + (lt >> 1) * 8 + lr;
                unsigned kb = (kk + (lt & 1) * 8) * 2;
                uint4 h4 = ldsm4(sb + 2 * ARR_B + nrow * ROWB + kb);
                uint4 l4 = ldsm4(sb + 3 * ARR_B + nrow * ROWB + kb);
                bh[2 * nf2]     = make_uint2(h4.x, h4.y);
                bh[2 * nf2 + 1] = make_uint2(h4.z, h4.w);
                bl[2 * nf2]     = make_uint2(l4.x, l4.y);
                bl[2 * nf2 + 1] = make_uint2(l4.z, l4.w);
            }
            #pragma unroll
            for (int mf = 0; mf < 4; mf++)
                #pragma unroll
                for (int nf = 0; nf < 4; nf++) {
                    mma_bf(acc[mf][nf], ah[mf], bh[nf]);
                    mma_bf(acc[mf][nf], al[mf], bh[nf]);
                    mma_bf(acc[mf][nf], ah[mf], bl[nf]);
                }
        }
        __syncthreads();
    }
    #undef LOAD3

    int qr = lane >> 2, qc = (lane & 3) * 2;
    #pragma unroll
    for (int mf = 0; mf < 4; mf++) {
        #pragma unroll
        for (int h = 0; h < 2; h++) {
            int gm = m0 + warpM * 64 + mf * 16 + h * 8 + qr;
            #pragma unroll
            for (int nf = 0; nf < 4; nf++) {
                int n = n0 + warpN * 32 + nf * 8 + qc;
                float v0 = acc[mf][nf][2 * h + 0] + bias[n];
                float v1 = acc[mf][nf][2 * h + 1] + bias[n + 1];
                if (EPI == EPI_RELU) { v0 = fmaxf(v0, 0.f); v1 = fmaxf(v1, 0.f); }
                size_t off = (size_t)gm * N + n;
                *(unsigned*)(outH + off) = hi2(v0, v1);
                *(unsigned*)(outL + off) = lo2(v0, v1);
                if (EPI == EPI_PACKZ)
                    *(unsigned*)(outF16 + off) = f16x2(v0, v1);
            }
        }
    }
}

// ---- fp16 single-MMA kernel (VQ scores / decoder) ----
#define STAGE1_B  (2 * ARR_B)
#define RED1_OFF  (2 * STAGE1_B)
#define IDX1_OFF  (RED1_OFF + 4096)
#define SMEM1_DYN (IDX1_OFF + 512)

enum { M1_RELU_F16 = 0, M1_SIG = 1, M1_ARGMIN = 2 };

template<bool GATHER, int EPI>
__global__ __launch_bounds__(256, 1)
void mm1_kernel(const __half* __restrict__ Af, const int* __restrict__ gidx,
                const __half* __restrict__ Bf,
                const float* __restrict__ bias,
                __half* __restrict__ outF16, float* __restrict__ outF,
                float* __restrict__ candV, int* __restrict__ candI,
                const float* __restrict__ cnorm,
                int K, int N, float ascale)
{
    extern __shared__ __align__(16) char dsm[];
    unsigned su = smem_u32(dsm);
    float* redV = (float*)(dsm + RED1_OFF);
    int*   redI = (int*)(dsm + RED1_OFF + 2048);
    int*   sIdx = (int*)(dsm + IDX1_OFF);

    int tid = threadIdx.x;
    int lane = tid & 31;
    int warp = tid >> 5;
    int warpM = warp >> 2, warpN = warp & 3;
    int m0 = blockIdx.y * 128;
    int n0 = blockIdx.x * 128;

    if (GATHER) {
        if (tid < 128) sIdx[tid] = gidx[m0 + tid];
        __syncthreads();
    }

    float acc[4][4][4];
    #pragma unroll
    for (int i = 0; i < 4; i++)
        #pragma unroll
        for (int j = 0; j < 4; j++)
            #pragma unroll
            for (int q = 0; q < 4; q++) acc[i][j][q] = 0.f;

    int S = K >> 5;

    // per stage: 1024 x 16B chunks (A:512, B:512), 4 per thread
    #define LOAD1(stg, k0v)                                                    \
    {                                                                          \
        int k0_ = (k0v);                                                       \
        _Pragma("unroll")                                                      \
        for (int j = 0; j < 4; j++) {                                          \
            int u = tid + 256 * j;                                             \
            int arr = u >> 9, v = u & 511, row = v >> 2, ch = v & 3;           \
            const __half* src;                                                 \
            int rg;                                                            \
            if (arr) { rg = n0 + row; src = Bf; }                              \
            else     { rg = GATHER ? sIdx[row] : (m0 + row); src = Af; }       \
            src += (size_t)rg * K + k0_ + ch * 8;                              \
            unsigned dst = su + (stg) * STAGE1_B + arr * ARR_B + row * ROWB + ch * 16; \
            CP_ASYNC16(dst, src);                                              \
        }                                                                      \
        CP_COMMIT();                                                           \
    }

    LOAD1(0, 0);
    for (int s = 0; s < S; s++) {
        if (s + 1 < S) LOAD1((s + 1) & 1, (s + 1) << 5);
        if (s + 1 < S) { CP_WAIT1(); } else { CP_WAIT0(); }
        __syncthreads();

        unsigned sb = su + (s & 1) * STAGE1_B;
        int lt = lane >> 3, lr = lane & 7;
        #pragma unroll
        for (int kk = 0; kk < 32; kk += 16) {
            uint4 af[4];
            uint2 bf[4];
            #pragma unroll
            for (int mf = 0; mf < 4; mf++) {
                int mrow = warpM * 64 + mf * 16 + (lt & 1) * 8 + lr;
                unsigned kb = (kk + (lt >> 1) * 8) * 2;
                af[mf] = ldsm4(sb + 0 * ARR_B + mrow * ROWB + kb);
            }
            #pragma unroll
            for (int nf2 = 0; nf2 < 2; nf2++) {
                int nrow = warpN * 32 + nf2 * 16 + (lt >> 1) * 8 + lr;
                unsigned kb = (kk + (lt & 1) * 8) * 2;
                uint4 h4 = ldsm4(sb + 1 * ARR_B + nrow * ROWB + kb);
                bf[2 * nf2]     = make_uint2(h4.x, h4.y);
                bf[2 * nf2 + 1] = make_uint2(h4.z, h4.w);
            }
            #pragma unroll
            for (int mf = 0; mf < 4; mf++)
                #pragma unroll
                for (int nf = 0; nf < 4; nf++)
                    mma_hf(acc[mf][nf], af[mf], bf[nf]);
        }
        __syncthreads();
    }
    #undef LOAD1

    int qr = lane >> 2, qc = (lane & 3) * 2;

    if (EPI == M1_ARGMIN) {
        float s2 = 2.f * ascale;
        #pragma unroll
        for (int mf = 0; mf < 4; mf++) {
            #pragma unroll
            for (int h = 0; h < 2; h++) {
                int mloc = warpM * 64 + mf * 16 + h * 8 + qr;
                float bv = 3.4e38f; int bi = 0;
                #pragma unroll
                for (int nf = 0; nf < 4; nf++) {
                    #pragma unroll
                    for (int p = 0; p < 2; p++) {
                        int n = n0 + warpN * 32 + nf * 8 + qc + p;
                        float sc = cnorm[n] - s2 * acc[mf][nf][2 * h + p];
                        if (sc < bv || (sc == bv && n < bi)) { bv = sc; bi = n; }
                    }
                }
                #pragma unroll
                for (int x = 1; x < 4; x <<= 1) {
                    float v2 = __shfl_xor_sync(0xFFFFFFFFu, bv, x);
                    int   i2 = __shfl_xor_sync(0xFFFFFFFFu, bi, x);
                    if (v2 < bv || (v2 == bv && i2 < bi)) { bv = v2; bi = i2; }
                }
                if ((lane & 3) == 0) {
                    redV[mloc * 4 + warpN] = bv;
                    redI[mloc * 4 + warpN] = bi;
                }
            }
        }
        __syncthreads();
        if (tid < 128) {
            float bv = 3.4e38f; int bi = 0;
            #pragma unroll
            for (int wq = 0; wq < 4; wq++) {
                float v = redV[tid * 4 + wq];
                int   i = redI[tid * 4 + wq];
                if (v < bv || (v == bv && i < bi)) { bv = v; bi = i; }
            }
            candV[(size_t)(m0 + tid) * NT_VQ + blockIdx.x] = bv;
            candI[(size_t)(m0 + tid) * NT_VQ + blockIdx.x] = bi;
        }
    } else {
        #pragma unroll
        for (int mf = 0; mf < 4; mf++) {
            #pragma unroll
            for (int h = 0; h < 2; h++) {
                int gm = m0 + warpM * 64 + mf * 16 + h * 8 + qr;
                #pragma unroll
                for (int nf = 0; nf < 4; nf++) {
                    int n = n0 + warpN * 32 + nf * 8 + qc;
                    float v0 = acc[mf][nf][2 * h + 0] * ascale + bias[n];
                    float v1 = acc[mf][nf][2 * h + 1] * ascale + bias[n + 1];
                    size_t off = (size_t)gm * N + n;
                    if (EPI == M1_SIG) {
                        v0 = 1.f / (1.f + __expf(-v0));
                        v1 = 1.f / (1.f + __expf(-v1));
                        *(float2*)(outF + off) = make_float2(v0, v1);
                    } else {
                        v0 = fmaxf(v0, 0.f); v1 = fmaxf(v1, 0.f);
                        *(unsigned*)(outF16 + off) = f16x2(v0, v1);
                    }
                }
            }
        }
    }
}

// per-row argmin over NT_VQ column-tile candidates
__global__ __launch_bounds__(256) void vqred_k() {
    int r = blockIdx.x * 256 + threadIdx.x;
    const float* cv = g_candV + (size_t)r * NT_VQ;
    const int*   ci = g_candI + (size_t)r * NT_VQ;
    float best = 3.4e38f; int bi = 0;
    #pragma unroll
    for (int t = 0; t < NT_VQ; t++) {
        float v = cv[t]; int i = ci[t];
        if (v < best || (v == best && i < bi)) { best = v; bi = i; }
    }
    g_idx[r] = bi;
}

// loss = 1.25 * mean((codebook[idx] - z)^2), z = hi + lo (bf16 split)
__global__ __launch_bounds__(256) void loss_partial_kernel(const float* __restrict__ CB) {
    __shared__ float red[256];
    int tid = threadIdx.x;
    int b = blockIdx.x;
    float s = 0.f;
    for (int e = tid; e < 64 * LAT_DIM; e += 256) {
        int r = b * 64 + (e >> 8);
        int d = e & 255;
        size_t o = (size_t)r * LAT_DIM + d;
        float z = __bfloat162float(g_Zh[o]) + __bfloat162float(g_Zl[o]);
        float diff = CB[(size_t)g_idx[r] * LAT_DIM + d] - z;
        s += diff * diff;
    }
    red[tid] = s;
    __syncthreads();
    for (int st = 128; st > 0; st >>= 1) {
        if (tid < st) red[tid] += red[tid + st];
        __syncthreads();
    }
    if (tid == 0) g_partials[b] = red[0];
}

__global__ __launch_bounds__(256) void loss_final_kernel(float* __restrict__ out) {
    __shared__ float red[256];
    int tid = threadIdx.x;
    red[tid] = g_partials[tid];
    __syncthreads();
    for (int st = 128; st > 0; st >>= 1) {
        if (tid < st) red[tid] += red[tid + st];
        __syncthreads();
    }
    if (tid == 0) out[0] = 1.25f * red[0] / ((float)BATCH_N * (float)LAT_DIM);
}

// ---------------------------------------------------------------------------
extern "C" void kernel_launch(void* const* d_in, const int* in_sizes, int n_in,
                              void* d_out, int out_size)
{
    (void)in_sizes; (void)n_in; (void)out_size;
    const float* x      = (const float*)d_in[0];
    const float* enc_w1 = (const float*)d_in[1];
    const float* enc_b1 = (const float*)d_in[2];
    const float* enc_w2 = (const float*)d_in[3];
    const float* enc_b2 = (const float*)d_in[4];
    const float* cbook  = (const float*)d_in[5];
    const float* dec_w1 = (const float*)d_in[6];
    const float* dec_b1 = (const float*)d_in[7];
    const float* dec_w2 = (const float*)d_in[8];
    const float* dec_b2 = (const float*)d_in[9];
    float* out = (float*)d_out;

    cudaFuncSetAttribute(mm3_kernel<EPI_RELU>,
                         cudaFuncAttributeMaxDynamicSharedMemorySize, SMEM_DYN);
    cudaFuncSetAttribute(mm3_kernel<EPI_PACKZ>,
                         cudaFuncAttributeMaxDynamicSharedMemorySize, SMEM_DYN);
    cudaFuncSetAttribute(mm1_kernel<false, M1_ARGMIN>,
                         cudaFuncAttributeMaxDynamicSharedMemorySize, SMEM1_DYN);
    cudaFuncSetAttribute(mm1_kernel<true,  M1_RELU_F16>,
                         cudaFuncAttributeMaxDynamicSharedMemorySize, SMEM1_DYN);
    cudaFuncSetAttribute(mm1_kernel<false, M1_SIG>,
                         cudaFuncAttributeMaxDynamicSharedMemorySize, SMEM1_DYN);

    __nv_bfloat16 *Xh, *Xl, *Hh, *Hl, *Zh, *Zl, *W1h, *W1l, *W2h, *W2l;
    __half *Zf, *HDf, *D1f, *D2f, *CBf;
    float *candV, *cnorm; int *candI, *idx;
    cudaGetSymbolAddress((void**)&Xh,  g_Xh);  cudaGetSymbolAddress((void**)&Xl,  g_Xl);
    cudaGetSymbolAddress((void**)&Hh,  g_Hh);  cudaGetSymbolAddress((void**)&Hl,  g_Hl);
    cudaGetSymbolAddress((void**)&Zh,  g_Zh);  cudaGetSymbolAddress((void**)&Zl,  g_Zl);
    cudaGetSymbolAddress((void**)&Zf,  g_Zf);
    cudaGetSymbolAddress((void**)&HDf, g_HDf);
    cudaGetSymbolAddress((void**)&W1h, g_W1h); cudaGetSymbolAddress((void**)&W1l, g_W1l);
    cudaGetSymbolAddress((void**)&W2h, g_W2h); cudaGetSymbolAddress((void**)&W2l, g_W2l);
    cudaGetSymbolAddress((void**)&D1f, g_D1f); cudaGetSymbolAddress((void**)&D2f, g_D2f);
    cudaGetSymbolAddress((void**)&CBf, g_CBf);
    cudaGetSymbolAddress((void**)&candV, g_candV);
    cudaGetSymbolAddress((void**)&candI, g_candI);
    cudaGetSymbolAddress((void**)&cnorm, g_cnorm);
    cudaGetSymbolAddress((void**)&idx,   g_idx);

    dim3 tb(32, 8);
    wsplit_t<<<dim3(HID_DIM / 32, IN_DIM / 32),  tb>>>(enc_w1, W1h, W1l, IN_DIM,  HID_DIM);
    wsplit_t<<<dim3(LAT_DIM / 32, HID_DIM / 32), tb>>>(enc_w2, W2h, W2l, HID_DIM, LAT_DIM);
    wsingle_t<<<dim3(HID_DIM / 32, LAT_DIM / 32), tb>>>(dec_w1, D1f, LAT_DIM, HID_DIM);
    wsingle_t<<<dim3(IN_DIM / 32,  HID_DIM / 32), tb>>>(dec_w2, D2f, HID_DIM, IN_DIM);
    split2_k<<<(BATCH_N * IN_DIM / 4) / 256, 256>>>(
        (const float4*)x, (uint2*)Xh, (uint2*)Xl, BATCH_N * IN_DIM / 4);
    cbf_k<<<(NUM_EMB * LAT_DIM / 4) / 256, 256>>>(
        (const float4*)cbook, (uint2*)CBf, NUM_EMB * LAT_DIM / 4);
    cnorm_kernel<<<NUM_EMB / 8, 256>>>(cbook);

    // encoder (bf16 split 3-MMA, z-path precision)
    mm3_kernel<EPI_RELU><<<dim3(HID_DIM / 128, BATCH_N / 128), 256, SMEM_DYN>>>(
        Xh, Xl, W1h, W1l, enc_b1, Hh, Hl, nullptr, IN_DIM, HID_DIM);
    mm3_kernel<EPI_PACKZ><<<dim3(LAT_DIM / 128, BATCH_N / 128), 256, SMEM_DYN>>>(
        Hh, Hl, W2h, W2l, enc_b2, Zh, Zl, Zf, HID_DIM, LAT_DIM);

    // vector quantizer (fp16 single-MMA; codebook prescaled by 2^10)
    mm1_kernel<false, M1_ARGMIN><<<dim3(NUM_EMB / 128, BATCH_N / 128), 256, SMEM1_DYN>>>(
        Zf, nullptr, CBf, nullptr, nullptr, nullptr,
        candV, candI, cnorm, LAT_DIM, NUM_EMB, 1.0f / CB_SCALE);
    vqred_k<<<BATCH_N / 256, 256>>>();

    // decoder (fp16 single-MMA; bias-dominated)
    mm1_kernel<true, M1_RELU_F16><<<dim3(HID_DIM / 128, BATCH_N / 128), 256, SMEM1_DYN>>>(
        CBf, idx, D1f, dec_b1, HDf, nullptr,
        nullptr, nullptr, nullptr, LAT_DIM, HID_DIM, 1.0f / CB_SCALE);
    mm1_kernel<false, M1_SIG><<<dim3(IN_DIM / 128, BATCH_N / 128), 256, SMEM1_DYN>>>(
        HDf, nullptr, D2f, dec_b2, nullptr, out,
        nullptr, nullptr, nullptr, HID_DIM, IN_DIM, 1.0f);

    // loss scalar -> last output element
    loss_partial_kernel<<<BATCH_N / 64, 256>>>(cbook);
    loss_final_kernel<<<1, 256>>>(out + (size_t)BATCH_N * IN_DIM);
}